// round 16
// baseline (speedup 1.0000x reference)
#include <cuda_runtime.h>

#define N_CELL 200000
#define N_WELL 512
#define E_CC   1600000
#define E_CW   65536
#define H      64
#define NEG_SLOPE 0.2f
#define N_TILE (N_CELL / 64)   // 3125
#define HS_STRIDE ((size_t)N_CELL * H)

// ---------------- scratch (double-buffered node state) ----------------
__device__ float g_hs[2 * N_CELL * H];
__device__ float g_as[2 * N_CELL];
__device__ float g_ad[2 * N_CELL];
__device__ float g_adw[N_WELL];
__device__ float g_k1[3], g_k0[3];
__device__ float g_W0[12 * H];
__device__ float g_b0[H];
__device__ int g_cc64, g_cw64;

// CSR scratch
__device__ int g_off[N_CELL + 1];
__device__ int g_cur[N_CELL];
__device__ int2 g_edge[E_CC];          // (src, attr bits) combined
__device__ int g_bsum[256];
__device__ int g_woff[N_WELL + 1];
__device__ int g_wcur[N_WELL];
__device__ int g_wsrcp[E_CW];

// ---------------- f32x2 helpers ----------------
__device__ __forceinline__ unsigned long long pack2(float a) {
    unsigned long long r;
    asm("mov.b64 %0, {%1, %1};" : "=l"(r) : "f"(a));
    return r;
}
__device__ __forceinline__ void ffma2(unsigned long long& d,
                                      unsigned long long a,
                                      unsigned long long b) {
    asm("fma.rn.f32x2 %0, %1, %2, %0;" : "+l"(d) : "l"(a), "l"(b));
}
__device__ __forceinline__ float2 unpack2(unsigned long long v) {
    float2 f;
    asm("mov.b64 {%0, %1}, %2;" : "=f"(f.x), "=f"(f.y) : "l"(v));
    return f;
}

__device__ __forceinline__ int ld_idx(const void* p, long long i, int is64) {
    return is64 ? (int)((const long long*)p)[i] : ((const int*)p)[i];
}

// ---------------- setup: detect + compute_k + prep_W0 + zero hist ----------------
__global__ void setup(const float* __restrict__ W_edge,
                      const float* __restrict__ b_edge,
                      const float* __restrict__ lin_edge,
                      const float* __restrict__ att_e,
                      const float* __restrict__ Wemb,
                      const float* __restrict__ bemb,
                      const float* __restrict__ lin0,
                      const void* cc, const void* cw) {
    int b = blockIdx.x;
    int tid = threadIdx.x;
    if (b == 0) {
        if (tid == 0) {
            const long long* q = (const long long*)cc;
            int ok = 1;
            for (int i = 0; i < 64; i++) {
                long long v = q[(long long)i * 25000];
                if (v < 0 || v >= N_CELL) { ok = 0; break; }
            }
            g_cc64 = ok;
            const long long* r = (const long long*)cw;
            ok = 1;
            for (int i = 0; i < 64; i++) {
                long long v = r[(long long)i * 1000];
                if (v < 0 || v >= N_CELL) { ok = 0; break; }
            }
            g_cw64 = ok;
        }
    } else if (b <= 3) {
        int l = b - 1;
        __shared__ float s1[H], s0[H];
        if (tid < H) {
            const float* L = lin_edge + l * H * H;
            const float* A = att_e + l * H;
            float r = 0.f;
            for (int j = 0; j < H; j++) r += L[tid * H + j] * A[j];
            s1[tid] = W_edge[tid] * r;
            s0[tid] = b_edge[tid] * r;
        }
        __syncthreads();
        if (tid == 0) {
            float k1 = 0.f, k0 = 0.f;
            for (int j = 0; j < H; j++) { k1 += s1[j]; k0 += s0[j]; }
            g_k1[l] = k1; g_k0[l] = k0;
        }
    } else if (b <= 7) {
        int idx = (b - 4) * 256 + tid;
        if (idx < 13 * 64) {
            int i = idx >> 6, c = idx & 63;
            float s = 0.f;
            if (i < 12) {
                for (int k = 0; k < H; k++) s += Wemb[i * H + k] * lin0[k * H + c];
                g_W0[i * H + c] = s;
            } else {
                for (int k = 0; k < H; k++) s += bemb[k] * lin0[k * H + c];
                g_b0[c] = s;
            }
        }
    } else {
        int i = (b - 8) * 256 + tid;
        if (i < N_CELL) g_cur[i] = 0;
        if (i < N_WELL) g_wcur[i] = 0;
    }
}

// ---------------- CSR build ----------------
__global__ void hist_all(const void* __restrict__ cc, const void* __restrict__ cw) {
    int e = blockIdx.x * blockDim.x + threadIdx.x;
    if (e < E_CC) {
        int d = ld_idx(cc, (long long)E_CC + e, g_cc64);
        atomicAdd(&g_cur[d], 1);
    } else if (e < E_CC + E_CW) {
        int e2 = e - E_CC;
        int d = ld_idx(cw, (long long)E_CW + e2, g_cw64);
        atomicAdd(&g_wcur[d], 1);
    }
}
__global__ void scan1() {
    __shared__ int sh[1024];
    int tid = threadIdx.x;
    int gid = blockIdx.x * 1024 + tid;
    int v = (gid < N_CELL) ? g_cur[gid] : 0;
    sh[tid] = v;
    __syncthreads();
    for (int off = 1; off < 1024; off <<= 1) {
        int t = (tid >= off) ? sh[tid - off] : 0;
        __syncthreads();
        sh[tid] += t;
        __syncthreads();
    }
    if (gid < N_CELL) g_off[gid] = sh[tid] - v;
    if (tid == 1023) g_bsum[blockIdx.x] = sh[1023];
}
__global__ void scan2p(int nblk) {
    __shared__ int sh[256];
    int tid = threadIdx.x;
    int v = tid < nblk ? g_bsum[tid] : 0;
    sh[tid] = v;
    __syncthreads();
    for (int off = 1; off < 256; off <<= 1) {
        int t = (tid >= off) ? sh[tid - off] : 0;
        __syncthreads();
        sh[tid] += t;
        __syncthreads();
    }
    if (tid < nblk) g_bsum[tid] = sh[tid] - v;
    if (tid == 0) g_off[N_CELL] = E_CC;
}
__global__ void scan3w() {
    if (blockIdx.x < 391) {
        int gid = blockIdx.x * 512 + threadIdx.x;
        if (gid >= N_CELL) return;
        int o = g_off[gid] + g_bsum[gid >> 10];
        g_off[gid] = o;
        g_cur[gid] = o;
    } else {
        __shared__ int sh[512];
        int tid = threadIdx.x;
        int v = g_wcur[tid];
        sh[tid] = v;
        __syncthreads();
        for (int off = 1; off < 512; off <<= 1) {
            int t = (tid >= off) ? sh[tid - off] : 0;
            __syncthreads();
            sh[tid] += t;
            __syncthreads();
        }
        g_woff[tid] = sh[tid] - v;
        g_wcur[tid] = sh[tid] - v;
        if (tid == 0) g_woff[N_WELL] = E_CW;
    }
}
__global__ void scatter_all(const void* __restrict__ cc,
                            const void* __restrict__ cw,
                            const float* __restrict__ attr) {
    int e = blockIdx.x * blockDim.x + threadIdx.x;
    if (e < E_CC) {
        int is64 = g_cc64;
        int s = ld_idx(cc, e, is64);
        int d = ld_idx(cc, (long long)E_CC + e, is64);
        int p = atomicAdd(&g_cur[d], 1);
        g_edge[p] = make_int2(s, __float_as_int(attr[e]));
    } else if (e < E_CC + E_CW) {
        int e2 = e - E_CC;
        int is64 = g_cw64;
        int s = ld_idx(cw, e2, is64);
        int d = ld_idx(cw, (long long)E_CW + e2, is64);
        int p = atomicAdd(&g_wcur[d], 1);
        g_wsrcp[p] = s;
    }
}

// ---------------- GEMM layer 0 -> buffer 0 (overlaps CSR) ----------------
__global__ __launch_bounds__(256) void gemm12(
    const float* __restrict__ x,
    const float* __restrict__ atts,
    const float* __restrict__ attd)
{
    __shared__ float shX[64][13];
    __shared__ float shW[12][64];
    __shared__ float shB[64];
    int tid = threadIdx.x;
    int r0 = blockIdx.x * 64;

    if (tid < 64) shB[tid] = g_b0[tid];
    for (int i = tid; i < 12 * 64; i += 256) shW[i >> 6][i & 63] = g_W0[i];
    for (int i = tid; i < 64 * 12; i += 256) shX[i / 12][i % 12] = x[(size_t)r0 * 12 + i];
    __syncthreads();

    int rg = tid >> 4, cg = tid & 15;
    int row0 = rg << 2, col0 = cg << 2;
    float acc[4][4];
    #pragma unroll
    for (int xx = 0; xx < 4; xx++)
        #pragma unroll
        for (int j = 0; j < 4; j++) acc[xx][j] = shB[col0 + j];

    #pragma unroll
    for (int k = 0; k < 12; k++) {
        float4 wv = *(const float4*)&shW[k][col0];
        float a0 = shX[row0][k], a1 = shX[row0 + 1][k];
        float a2 = shX[row0 + 2][k], a3 = shX[row0 + 3][k];
        acc[0][0] += a0 * wv.x; acc[0][1] += a0 * wv.y; acc[0][2] += a0 * wv.z; acc[0][3] += a0 * wv.w;
        acc[1][0] += a1 * wv.x; acc[1][1] += a1 * wv.y; acc[1][2] += a1 * wv.z; acc[1][3] += a1 * wv.w;
        acc[2][0] += a2 * wv.x; acc[2][1] += a2 * wv.y; acc[2][2] += a2 * wv.z; acc[2][3] += a2 * wv.w;
        acc[3][0] += a3 * wv.x; acc[3][1] += a3 * wv.y; acc[3][2] += a3 * wv.z; acc[3][3] += a3 * wv.w;
    }

    #pragma unroll
    for (int xx = 0; xx < 4; xx++) {
        float ps = acc[xx][0] * atts[col0] + acc[xx][1] * atts[col0 + 1]
                 + acc[xx][2] * atts[col0 + 2] + acc[xx][3] * atts[col0 + 3];
        float pd = acc[xx][0] * attd[col0] + acc[xx][1] * attd[col0 + 1]
                 + acc[xx][2] * attd[col0 + 2] + acc[xx][3] * attd[col0 + 3];
        #pragma unroll
        for (int off = 8; off; off >>= 1) {
            ps += __shfl_xor_sync(0xffffffffu, ps, off);
            pd += __shfl_xor_sync(0xffffffffu, pd, off);
        }
        if ((tid & 15) == 0) {
            g_as[r0 + row0 + xx] = ps;
            g_ad[r0 + row0 + xx] = pd;
        }
        *(float4*)&g_hs[(size_t)(r0 + row0 + xx) * H + col0] =
            make_float4(acc[xx][0], acc[xx][1], acc[xx][2], acc[xx][3]);
    }
}

// ---------------- well prep (overlaps CSR) ----------------
__global__ void well_prep(const float* __restrict__ well_x,
                          const float* __restrict__ Ww,
                          const float* __restrict__ bw,
                          const float* __restrict__ wc_lin,
                          const float* __restrict__ attd) {
    int r = blockIdx.x;
    int c = threadIdx.x;
    __shared__ float hw[64];
    __shared__ float red[64];
    float acc = bw[c];
    for (int i = 0; i < 8; i++) acc += well_x[r * 8 + i] * Ww[i * H + c];
    hw[c] = acc;
    __syncthreads();
    float hd = 0.f;
    for (int k = 0; k < H; k++) hd += hw[k] * wc_lin[k * H + c];
    red[c] = hd * attd[c];
    __syncthreads();
    for (int off = 32; off > 0; off >>= 1) {
        if (c < off) red[c] += red[c + off];
        __syncthreads();
    }
    if (c == 0) g_adw[r] = red[0];
}

// ---------------- FUSED: edge pass l (read buf_in) + GEMM next layer (write buf_out) ----------------
// W read from GLOBAL (L1-resident broadcast) -> smem/block 17.4KB -> 8 blocks/SM.
__global__ __launch_bounds__(256) void edge_gemm(
    int l, int buf_in,
    const float* __restrict__ W,
    const float* __restrict__ atts,
    const float* __restrict__ attd,
    const float* __restrict__ bias)
{
    __shared__ float shHT[64][68];   // [feature][row]
    int tid = threadIdx.x;
    int lane = tid & 31;
    int wid = tid >> 5;
    int half = lane >> 4, li = lane & 15;
    int r0 = blockIdx.x * 64;
    float k1 = g_k1[l], k0 = g_k0[l];

    const float* hs_in = g_hs + (size_t)buf_in * HS_STRIDE;
    const float* as_in = g_as + (size_t)buf_in * N_CELL;
    const float* ad_in = g_ad + (size_t)buf_in * N_CELL;
    int buf_out = buf_in ^ 1;
    float* hs_out = g_hs + (size_t)buf_out * HS_STRIDE;
    float* as_out = g_as + (size_t)buf_out * N_CELL;
    float* ad_out = g_ad + (size_t)buf_out * N_CELL;

    float4 bv = ((const float4*)bias)[li];

    // edge aggregation: warp wid handles dsts r0 + wid*8 .. +7
    for (int i = 0; i < 8; i++) {
        int w = r0 + (wid << 3) + i;
        int beg = g_off[w], end = g_off[w + 1];
        int deg = end - beg;
        float adv = ad_in[w];
        float ssum = 0.f;
        float4 acc = make_float4(0.f, 0.f, 0.f, 0.f);

        for (int base = 0; base < deg; base += 32) {
            int n = min(32, deg - base);
            float ex = 0.f;
            int src = 0;
            if (lane < n) {
                int2 ev = g_edge[beg + base + lane];
                src = ev.x;
                float al = as_in[src] + adv + k1 * __int_as_float(ev.y) + k0;
                al = al > 0.f ? al : NEG_SLOPE * al;
                ex = __expf(al);
            }
            float cs = ex;
            #pragma unroll
            for (int off = 16; off; off >>= 1) cs += __shfl_xor_sync(0xffffffffu, cs, off);
            ssum += cs;
            int iters = (n + 1) >> 1;
            for (int t = 0; t < iters; t++) {
                int j = 2 * t + half;
                int jj = j < n ? j : 0;
                float wt = __shfl_sync(0xffffffffu, ex, jj);
                int s2 = __shfl_sync(0xffffffffu, src, jj);
                if (j < n) {
                    float4 v = *(const float4*)&hs_in[(size_t)s2 * H + li * 4];
                    acc.x += v.x * wt; acc.y += v.y * wt; acc.z += v.z * wt; acc.w += v.w * wt;
                }
            }
        }
        acc.x += __shfl_down_sync(0xffffffffu, acc.x, 16);
        acc.y += __shfl_down_sync(0xffffffffu, acc.y, 16);
        acc.z += __shfl_down_sync(0xffffffffu, acc.z, 16);
        acc.w += __shfl_down_sync(0xffffffffu, acc.w, 16);
        if (lane < 16) {
            float sinv = deg > 0 ? 1.f / ssum : 0.f;
            int row = (wid << 3) + i;
            shHT[li * 4 + 0][row] = fmaxf(acc.x * sinv + bv.x, 0.f);
            shHT[li * 4 + 1][row] = fmaxf(acc.y * sinv + bv.y, 0.f);
            shHT[li * 4 + 2][row] = fmaxf(acc.z * sinv + bv.z, 0.f);
            shHT[li * 4 + 3][row] = fmaxf(acc.w * sinv + bv.w, 0.f);
        }
    }
    __syncthreads();

    // GEMM: hs_next = shHT^T @ W (W from global/L1), fused attention epilogue
    int rg = tid >> 4, cg = tid & 15;
    int row0 = rg << 2, col0 = cg << 2;
    float as0 = atts[col0], as1 = atts[col0 + 1], as2 = atts[col0 + 2], as3 = atts[col0 + 3];
    float ad0 = attd[col0], ad1 = attd[col0 + 1], ad2 = attd[col0 + 2], ad3 = attd[col0 + 3];

    unsigned long long acc2[4][2] = {};
    #pragma unroll 8
    for (int k = 0; k < H; k++) {
        float4 av = *(const float4*)&shHT[k][row0];
        ulonglong2 wv = __ldg((const ulonglong2*)&W[k * H + col0]);
        unsigned long long a0 = pack2(av.x), a1 = pack2(av.y);
        unsigned long long a2 = pack2(av.z), a3 = pack2(av.w);
        ffma2(acc2[0][0], a0, wv.x); ffma2(acc2[0][1], a0, wv.y);
        ffma2(acc2[1][0], a1, wv.x); ffma2(acc2[1][1], a1, wv.y);
        ffma2(acc2[2][0], a2, wv.x); ffma2(acc2[2][1], a2, wv.y);
        ffma2(acc2[3][0], a3, wv.x); ffma2(acc2[3][1], a3, wv.y);
    }

    #pragma unroll
    for (int xx = 0; xx < 4; xx++) {
        float2 p0 = unpack2(acc2[xx][0]);
        float2 p1 = unpack2(acc2[xx][1]);
        float ps = p0.x * as0 + p0.y * as1 + p1.x * as2 + p1.y * as3;
        float pd = p0.x * ad0 + p0.y * ad1 + p1.x * ad2 + p1.y * ad3;
        #pragma unroll
        for (int off = 8; off; off >>= 1) {
            ps += __shfl_xor_sync(0xffffffffu, ps, off);
            pd += __shfl_xor_sync(0xffffffffu, pd, off);
        }
        if ((tid & 15) == 0) {
            as_out[r0 + row0 + xx] = ps;
            ad_out[r0 + row0 + xx] = pd;
        }
        *(float4*)&hs_out[(size_t)(r0 + row0 + xx) * H + col0] =
            make_float4(p0.x, p0.y, p1.x, p1.y);
    }
}

// ---------------- well tail: edge aggregation + wc_bias + MLP, one block per well ----------------
__global__ __launch_bounds__(64) void well_tail(
    int buf_in,
    const float* __restrict__ wc_bias,
    const float* __restrict__ W1,
    const float* __restrict__ b1,
    const float* __restrict__ W2,
    const float* __restrict__ b2,
    float* __restrict__ out)
{
    __shared__ float hwell[64];
    __shared__ float t1[64];
    int r = blockIdx.x;
    int tid = threadIdx.x;
    const float* hs_in = g_hs + (size_t)buf_in * HS_STRIDE;
    const float* as_in = g_as + (size_t)buf_in * N_CELL;

    if (tid < 32) {
        int lane = tid;
        int half = lane >> 4, li = lane & 15;
        int beg = g_woff[r], end = g_woff[r + 1];
        int deg = end - beg;
        float adv = g_adw[r];
        float ssum = 0.f;
        float4 acc = make_float4(0.f, 0.f, 0.f, 0.f);

        for (int base = 0; base < deg; base += 32) {
            int n = min(32, deg - base);
            float ex = 0.f;
            int src = 0;
            if (lane < n) {
                src = g_wsrcp[beg + base + lane];
                float al = as_in[src] + adv;
                al = al > 0.f ? al : NEG_SLOPE * al;
                ex = __expf(al);
            }
            float cs = ex;
            #pragma unroll
            for (int off = 16; off; off >>= 1) cs += __shfl_xor_sync(0xffffffffu, cs, off);
            ssum += cs;
            int iters = (n + 1) >> 1;
            for (int t = 0; t < iters; t++) {
                int j = 2 * t + half;
                int jj = j < n ? j : 0;
                float wt = __shfl_sync(0xffffffffu, ex, jj);
                int s2 = __shfl_sync(0xffffffffu, src, jj);
                if (j < n) {
                    float4 v = *(const float4*)&hs_in[(size_t)s2 * H + li * 4];
                    acc.x += v.x * wt; acc.y += v.y * wt; acc.z += v.z * wt; acc.w += v.w * wt;
                }
            }
        }
        acc.x += __shfl_down_sync(0xffffffffu, acc.x, 16);
        acc.y += __shfl_down_sync(0xffffffffu, acc.y, 16);
        acc.z += __shfl_down_sync(0xffffffffu, acc.z, 16);
        acc.w += __shfl_down_sync(0xffffffffu, acc.w, 16);
        if (lane < 16) {
            float sinv = deg > 0 ? 1.f / ssum : 0.f;
            float4 wb = ((const float4*)wc_bias)[li];
            hwell[li * 4 + 0] = acc.x * sinv + wb.x;
            hwell[li * 4 + 1] = acc.y * sinv + wb.y;
            hwell[li * 4 + 2] = acc.z * sinv + wb.z;
            hwell[li * 4 + 3] = acc.w * sinv + wb.w;
        }
    }
    __syncthreads();

    float a = b1[tid];
    for (int k = 0; k < H; k++) a += hwell[k] * W1[k * H + tid];
    t1[tid] = fmaxf(a, 0.f);
    __syncthreads();
    for (int o = tid; o < 75; o += 64) {
        float acc = b2[o];
        for (int k = 0; k < H; k++) acc += t1[k] * W2[k * 75 + o];
        out[r * 75 + o] = acc;
    }
}

// ---------------- launcher ----------------
extern "C" void kernel_launch(void* const* d_in, const int* in_sizes, int n_in,
                              void* d_out, int out_size) {
    const void* cc_idx = nullptr;
    const void* cw_idx = nullptr;
    const float *cell_x = nullptr, *attr = nullptr, *W_cell_emb = nullptr,
                *W_well_emb = nullptr, *mlp_W2 = nullptr, *mlp_b2 = nullptr;
    const float* a12288[2] = {nullptr, nullptr};
    const float* a4096[3]  = {nullptr, nullptr, nullptr};
    const float* a192[4]   = {nullptr, nullptr, nullptr, nullptr};
    const float* a64[8]    = {nullptr, nullptr, nullptr, nullptr,
                              nullptr, nullptr, nullptr, nullptr};
    int n12288 = 0, n4096 = 0, n192 = 0, n64 = 0;
    int fsz[40]; int nf = 0;

    for (int i = 0; i < n_in; i++) {
        int sz = in_sizes[i];
        const float* p = (const float*)d_in[i];
        switch (sz) {
            case 2 * E_CC: cc_idx = d_in[i]; continue;
            case 2 * E_CW: cw_idx = d_in[i]; continue;
            case 2400000:  cell_x = p; break;
            case 1600000:  attr = p; break;
            case 768:      W_cell_emb = p; break;
            case 512:      W_well_emb = p; break;
            case 4800:     mlp_W2 = p; break;
            case 75:       mlp_b2 = p; break;
            case 12288:    if (n12288 < 2) a12288[n12288++] = p; break;
            case 4096:     if (n4096 < 3)  a4096[n4096++]   = p; break;
            case 192:      if (n192 < 4)   a192[n192++]     = p; break;
            case 64:       if (n64 < 8)    a64[n64++]       = p; break;
            default: break;
        }
        if (nf < 40) fsz[nf++] = sz;
    }

    int ord = 0;
    if (nf > 0 && fsz[0] == 768) ord = 1;
    else if (nf > 3 && fsz[0] == 64 && fsz[3] == 1600000) ord = 2;

    const float* conv_lin      = a12288[0];
    const float* conv_lin_edge = a12288[1];

    const float *conv_att_src, *conv_att_dst, *conv_att_edge, *conv_bias;
    if (ord == 0) { conv_att_src = a192[0]; conv_att_dst = a192[1];
                    conv_att_edge = a192[2]; conv_bias = a192[3]; }
    else          { conv_att_dst = a192[0]; conv_att_edge = a192[1];
                    conv_att_src = a192[2]; conv_bias = a192[3]; }

    const float *well_x, *wc_lin, *mlp_W1;
    if (ord == 0) { well_x = a4096[0]; wc_lin = a4096[1]; mlp_W1 = a4096[2]; }
    else          { mlp_W1 = a4096[0]; wc_lin = a4096[1]; well_x = a4096[2]; }

    const float *b_cell_emb, *b_well_emb, *W_edge_emb, *b_edge_emb,
                *wc_att_src, *wc_att_dst, *wc_bias, *mlp_b1;
    if (ord == 0) {
        b_cell_emb = a64[0]; b_well_emb = a64[1]; W_edge_emb = a64[2];
        b_edge_emb = a64[3]; wc_att_src = a64[4]; wc_att_dst = a64[5];
        wc_bias = a64[6]; mlp_b1 = a64[7];
    } else if (ord == 1) {
        W_edge_emb = a64[0]; b_cell_emb = a64[1]; b_edge_emb = a64[2];
        b_well_emb = a64[3]; mlp_b1 = a64[4]; wc_att_dst = a64[5];
        wc_att_src = a64[6]; wc_bias = a64[7];
    } else {
        b_cell_emb = a64[0]; b_edge_emb = a64[1]; b_well_emb = a64[2];
        mlp_b1 = a64[3]; W_edge_emb = a64[4]; wc_att_dst = a64[5];
        wc_att_src = a64[6]; wc_bias = a64[7];
    }

    // one-time host-side resources (no device memory)
    static cudaStream_t s_side = nullptr;
    static cudaEvent_t e_det = nullptr, e_csr = nullptr;
    if (!s_side) {
        cudaStreamCreateWithFlags(&s_side, cudaStreamNonBlocking);
        cudaEventCreateWithFlags(&e_det, cudaEventDisableTiming);
        cudaEventCreateWithFlags(&e_csr, cudaEventDisableTiming);
    }

    const int NBLK_SCAN = (N_CELL + 1023) / 1024;   // 196
    const int NB_EALL = (E_CC + E_CW) / 256;        // 6506

    // main: setup
    setup<<<8 + (N_CELL + 255) / 256, 256>>>(
        W_edge_emb, b_edge_emb, conv_lin_edge, conv_att_edge,
        W_cell_emb, b_cell_emb, conv_lin, cc_idx, cw_idx);
    cudaEventRecord(e_det, 0);

    // side: CSR build
    cudaStreamWaitEvent(s_side, e_det, 0);
    hist_all<<<NB_EALL, 256, 0, s_side>>>(cc_idx, cw_idx);
    scan1<<<NBLK_SCAN, 1024, 0, s_side>>>();
    scan2p<<<1, 256, 0, s_side>>>(NBLK_SCAN);
    scan3w<<<392, 512, 0, s_side>>>();
    scatter_all<<<NB_EALL, 256, 0, s_side>>>(cc_idx, cw_idx, attr);
    cudaEventRecord(e_csr, s_side);

    // main (overlaps CSR): layer-0 GEMM (writes buf 0) + well prep
    gemm12<<<N_TILE, 256>>>(cell_x, conv_att_src, conv_att_dst);
    well_prep<<<N_WELL, 64>>>(well_x, W_well_emb, b_well_emb, wc_lin, wc_att_dst);

    // join, then fused edge+gemm chain (ping-pong buffers: 0->1->0->1)
    cudaStreamWaitEvent(0, e_csr, 0);
    edge_gemm<<<N_TILE, 256>>>(0, 0, conv_lin + 1 * H * H,
                               conv_att_src + 64, conv_att_dst + 64, conv_bias);
    edge_gemm<<<N_TILE, 256>>>(1, 1, conv_lin + 2 * H * H,
                               conv_att_src + 128, conv_att_dst + 128, conv_bias + 64);
    edge_gemm<<<N_TILE, 256>>>(2, 0, wc_lin,
                               wc_att_src, wc_att_dst, conv_bias + 128);
    well_tail<<<N_WELL, 64>>>(1, wc_bias, mlp_W1, mlp_b1, mlp_W2, mlp_b2,
                              (float*)d_out);
}

// round 17
// speedup vs baseline: 1.0272x; 1.0272x over previous
#include <cuda_runtime.h>

#define N_CELL 200000
#define N_WELL 512
#define E_CC   1600000
#define E_CW   65536
#define H      64
#define NEG_SLOPE 0.2f
#define N_TILE (N_CELL / 64)   // 3125
#define HS_STRIDE ((size_t)N_CELL * H)

// ---------------- scratch (double-buffered node state) ----------------
__device__ float g_hs[2 * N_CELL * H];
__device__ float g_as[2 * N_CELL];
__device__ float g_ad[2 * N_CELL];
__device__ float g_adw[N_WELL];
__device__ float g_k1[3], g_k0[3];
__device__ float g_W0[12 * H];
__device__ float g_b0[H];
__device__ int g_cc64, g_cw64;

// CSR scratch
__device__ int g_off[N_CELL + 1];
__device__ int g_cur[N_CELL];
__device__ int2 g_edge[E_CC];          // (src, attr bits) combined
__device__ int g_bsum[256];
__device__ int g_woff[N_WELL + 1];
__device__ int g_wcur[N_WELL];
__device__ int g_wsrcp[E_CW];

// ---------------- f32x2 helpers ----------------
__device__ __forceinline__ unsigned long long pack2(float a) {
    unsigned long long r;
    asm("mov.b64 %0, {%1, %1};" : "=l"(r) : "f"(a));
    return r;
}
__device__ __forceinline__ void ffma2(unsigned long long& d,
                                      unsigned long long a,
                                      unsigned long long b) {
    asm("fma.rn.f32x2 %0, %1, %2, %0;" : "+l"(d) : "l"(a), "l"(b));
}
__device__ __forceinline__ float2 unpack2(unsigned long long v) {
    float2 f;
    asm("mov.b64 {%0, %1}, %2;" : "=f"(f.x), "=f"(f.y) : "l"(v));
    return f;
}

__device__ __forceinline__ int ld_idx(const void* p, long long i, int is64) {
    return is64 ? (int)((const long long*)p)[i] : ((const int*)p)[i];
}

// ---------------- setup: detect + compute_k + prep_W0 + zero hist ----------------
__global__ void setup(const float* __restrict__ W_edge,
                      const float* __restrict__ b_edge,
                      const float* __restrict__ lin_edge,
                      const float* __restrict__ att_e,
                      const float* __restrict__ Wemb,
                      const float* __restrict__ bemb,
                      const float* __restrict__ lin0,
                      const void* cc, const void* cw) {
    int b = blockIdx.x;
    int tid = threadIdx.x;
    if (b == 0) {
        if (tid == 0) {
            const long long* q = (const long long*)cc;
            int ok = 1;
            for (int i = 0; i < 64; i++) {
                long long v = q[(long long)i * 25000];
                if (v < 0 || v >= N_CELL) { ok = 0; break; }
            }
            g_cc64 = ok;
            const long long* r = (const long long*)cw;
            ok = 1;
            for (int i = 0; i < 64; i++) {
                long long v = r[(long long)i * 1000];
                if (v < 0 || v >= N_CELL) { ok = 0; break; }
            }
            g_cw64 = ok;
        }
    } else if (b <= 3) {
        int l = b - 1;
        __shared__ float s1[H], s0[H];
        if (tid < H) {
            const float* L = lin_edge + l * H * H;
            const float* A = att_e + l * H;
            float r = 0.f;
            for (int j = 0; j < H; j++) r += L[tid * H + j] * A[j];
            s1[tid] = W_edge[tid] * r;
            s0[tid] = b_edge[tid] * r;
        }
        __syncthreads();
        if (tid == 0) {
            float k1 = 0.f, k0 = 0.f;
            for (int j = 0; j < H; j++) { k1 += s1[j]; k0 += s0[j]; }
            g_k1[l] = k1; g_k0[l] = k0;
        }
    } else if (b <= 7) {
        int idx = (b - 4) * 256 + tid;
        if (idx < 13 * 64) {
            int i = idx >> 6, c = idx & 63;
            float s = 0.f;
            if (i < 12) {
                for (int k = 0; k < H; k++) s += Wemb[i * H + k] * lin0[k * H + c];
                g_W0[i * H + c] = s;
            } else {
                for (int k = 0; k < H; k++) s += bemb[k] * lin0[k * H + c];
                g_b0[c] = s;
            }
        }
    } else {
        int i = (b - 8) * 256 + tid;
        if (i < N_CELL) g_cur[i] = 0;
        if (i < N_WELL) g_wcur[i] = 0;
    }
}

// ---------------- CSR build ----------------
__global__ void hist_all(const void* __restrict__ cc, const void* __restrict__ cw) {
    int e = blockIdx.x * blockDim.x + threadIdx.x;
    if (e < E_CC) {
        int d = ld_idx(cc, (long long)E_CC + e, g_cc64);
        atomicAdd(&g_cur[d], 1);
    } else if (e < E_CC + E_CW) {
        int e2 = e - E_CC;
        int d = ld_idx(cw, (long long)E_CW + e2, g_cw64);
        atomicAdd(&g_wcur[d], 1);
    }
}
__global__ void scan1() {
    __shared__ int sh[1024];
    int tid = threadIdx.x;
    int gid = blockIdx.x * 1024 + tid;
    int v = (gid < N_CELL) ? g_cur[gid] : 0;
    sh[tid] = v;
    __syncthreads();
    for (int off = 1; off < 1024; off <<= 1) {
        int t = (tid >= off) ? sh[tid - off] : 0;
        __syncthreads();
        sh[tid] += t;
        __syncthreads();
    }
    if (gid < N_CELL) g_off[gid] = sh[tid] - v;
    if (tid == 1023) g_bsum[blockIdx.x] = sh[1023];
}
__global__ void scan2p(int nblk) {
    __shared__ int sh[256];
    int tid = threadIdx.x;
    int v = tid < nblk ? g_bsum[tid] : 0;
    sh[tid] = v;
    __syncthreads();
    for (int off = 1; off < 256; off <<= 1) {
        int t = (tid >= off) ? sh[tid - off] : 0;
        __syncthreads();
        sh[tid] += t;
        __syncthreads();
    }
    if (tid < nblk) g_bsum[tid] = sh[tid] - v;
    if (tid == 0) g_off[N_CELL] = E_CC;
}
__global__ void scan3w() {
    if (blockIdx.x < 391) {
        int gid = blockIdx.x * 512 + threadIdx.x;
        if (gid >= N_CELL) return;
        int o = g_off[gid] + g_bsum[gid >> 10];
        g_off[gid] = o;
        g_cur[gid] = o;
    } else {
        __shared__ int sh[512];
        int tid = threadIdx.x;
        int v = g_wcur[tid];
        sh[tid] = v;
        __syncthreads();
        for (int off = 1; off < 512; off <<= 1) {
            int t = (tid >= off) ? sh[tid - off] : 0;
            __syncthreads();
            sh[tid] += t;
            __syncthreads();
        }
        g_woff[tid] = sh[tid] - v;
        g_wcur[tid] = sh[tid] - v;
        if (tid == 0) g_woff[N_WELL] = E_CW;
    }
}
__global__ void scatter_all(const void* __restrict__ cc,
                            const void* __restrict__ cw,
                            const float* __restrict__ attr) {
    int e = blockIdx.x * blockDim.x + threadIdx.x;
    if (e < E_CC) {
        int is64 = g_cc64;
        int s = ld_idx(cc, e, is64);
        int d = ld_idx(cc, (long long)E_CC + e, is64);
        int p = atomicAdd(&g_cur[d], 1);
        g_edge[p] = make_int2(s, __float_as_int(attr[e]));
    } else if (e < E_CC + E_CW) {
        int e2 = e - E_CC;
        int is64 = g_cw64;
        int s = ld_idx(cw, e2, is64);
        int d = ld_idx(cw, (long long)E_CW + e2, is64);
        int p = atomicAdd(&g_wcur[d], 1);
        g_wsrcp[p] = s;
    }
}

// ---------------- GEMM layer 0 -> buffer 0 (overlaps CSR) ----------------
__global__ __launch_bounds__(256) void gemm12(
    const float* __restrict__ x,
    const float* __restrict__ atts,
    const float* __restrict__ attd)
{
    __shared__ float shX[64][13];
    __shared__ float shW[12][64];
    __shared__ float shB[64];
    int tid = threadIdx.x;
    int r0 = blockIdx.x * 64;

    if (tid < 64) shB[tid] = g_b0[tid];
    for (int i = tid; i < 12 * 64; i += 256) shW[i >> 6][i & 63] = g_W0[i];
    for (int i = tid; i < 64 * 12; i += 256) shX[i / 12][i % 12] = x[(size_t)r0 * 12 + i];
    __syncthreads();

    int rg = tid >> 4, cg = tid & 15;
    int row0 = rg << 2, col0 = cg << 2;
    float acc[4][4];
    #pragma unroll
    for (int xx = 0; xx < 4; xx++)
        #pragma unroll
        for (int j = 0; j < 4; j++) acc[xx][j] = shB[col0 + j];

    #pragma unroll
    for (int k = 0; k < 12; k++) {
        float4 wv = *(const float4*)&shW[k][col0];
        float a0 = shX[row0][k], a1 = shX[row0 + 1][k];
        float a2 = shX[row0 + 2][k], a3 = shX[row0 + 3][k];
        acc[0][0] += a0 * wv.x; acc[0][1] += a0 * wv.y; acc[0][2] += a0 * wv.z; acc[0][3] += a0 * wv.w;
        acc[1][0] += a1 * wv.x; acc[1][1] += a1 * wv.y; acc[1][2] += a1 * wv.z; acc[1][3] += a1 * wv.w;
        acc[2][0] += a2 * wv.x; acc[2][1] += a2 * wv.y; acc[2][2] += a2 * wv.z; acc[2][3] += a2 * wv.w;
        acc[3][0] += a3 * wv.x; acc[3][1] += a3 * wv.y; acc[3][2] += a3 * wv.z; acc[3][3] += a3 * wv.w;
    }

    #pragma unroll
    for (int xx = 0; xx < 4; xx++) {
        float ps = acc[xx][0] * atts[col0] + acc[xx][1] * atts[col0 + 1]
                 + acc[xx][2] * atts[col0 + 2] + acc[xx][3] * atts[col0 + 3];
        float pd = acc[xx][0] * attd[col0] + acc[xx][1] * attd[col0 + 1]
                 + acc[xx][2] * attd[col0 + 2] + acc[xx][3] * attd[col0 + 3];
        #pragma unroll
        for (int off = 8; off; off >>= 1) {
            ps += __shfl_xor_sync(0xffffffffu, ps, off);
            pd += __shfl_xor_sync(0xffffffffu, pd, off);
        }
        if ((tid & 15) == 0) {
            g_as[r0 + row0 + xx] = ps;
            g_ad[r0 + row0 + xx] = pd;
        }
        *(float4*)&g_hs[(size_t)(r0 + row0 + xx) * H + col0] =
            make_float4(acc[xx][0], acc[xx][1], acc[xx][2], acc[xx][3]);
    }
}

// ---------------- well prep (overlaps CSR) ----------------
__global__ void well_prep(const float* __restrict__ well_x,
                          const float* __restrict__ Ww,
                          const float* __restrict__ bw,
                          const float* __restrict__ wc_lin,
                          const float* __restrict__ attd) {
    int r = blockIdx.x;
    int c = threadIdx.x;
    __shared__ float hw[64];
    __shared__ float red[64];
    float acc = bw[c];
    for (int i = 0; i < 8; i++) acc += well_x[r * 8 + i] * Ww[i * H + c];
    hw[c] = acc;
    __syncthreads();
    float hd = 0.f;
    for (int k = 0; k < H; k++) hd += hw[k] * wc_lin[k * H + c];
    red[c] = hd * attd[c];
    __syncthreads();
    for (int off = 32; off > 0; off >>= 1) {
        if (c < off) red[c] += red[c + off];
        __syncthreads();
    }
    if (c == 0) g_adw[r] = red[0];
}

// ---------------- FUSED: edge pass l (read buf_in) + GEMM next layer (write buf_out) ----------------
// shW restored to smem (R16's W-from-global was the regression).
__global__ __launch_bounds__(256) void edge_gemm(
    int l, int buf_in,
    const float* __restrict__ W,
    const float* __restrict__ atts,
    const float* __restrict__ attd,
    const float* __restrict__ bias)
{
    __shared__ float shHT[64][68];   // [feature][row]
    __shared__ float shW[64][64];
    int tid = threadIdx.x;
    int lane = tid & 31;
    int wid = tid >> 5;
    int half = lane >> 4, li = lane & 15;
    int r0 = blockIdx.x * 64;
    float k1 = g_k1[l], k0 = g_k0[l];

    const float* hs_in = g_hs + (size_t)buf_in * HS_STRIDE;
    const float* as_in = g_as + (size_t)buf_in * N_CELL;
    const float* ad_in = g_ad + (size_t)buf_in * N_CELL;
    int buf_out = buf_in ^ 1;
    float* hs_out = g_hs + (size_t)buf_out * HS_STRIDE;
    float* as_out = g_as + (size_t)buf_out * N_CELL;
    float* ad_out = g_ad + (size_t)buf_out * N_CELL;

    // W tile load (independent of edge work)
    const float4* W4 = (const float4*)W;
    for (int i = tid; i < 1024; i += 256) {
        int k = i >> 4, c = (i & 15) << 2;
        *(float4*)&shW[k][c] = W4[i];
    }
    float4 bv = ((const float4*)bias)[li];

    // edge aggregation: warp wid handles dsts r0 + wid*8 .. +7
    for (int i = 0; i < 8; i++) {
        int w = r0 + (wid << 3) + i;
        int beg = g_off[w], end = g_off[w + 1];
        int deg = end - beg;
        float adv = ad_in[w];
        float ssum = 0.f;
        float4 acc = make_float4(0.f, 0.f, 0.f, 0.f);

        for (int base = 0; base < deg; base += 32) {
            int n = min(32, deg - base);
            float ex = 0.f;
            int src = 0;
            if (lane < n) {
                int2 ev = g_edge[beg + base + lane];
                src = ev.x;
                float al = as_in[src] + adv + k1 * __int_as_float(ev.y) + k0;
                al = al > 0.f ? al : NEG_SLOPE * al;
                ex = __expf(al);
            }
            float cs = ex;
            #pragma unroll
            for (int off = 16; off; off >>= 1) cs += __shfl_xor_sync(0xffffffffu, cs, off);
            ssum += cs;
            int iters = (n + 1) >> 1;
            for (int t = 0; t < iters; t++) {
                int j = 2 * t + half;
                int jj = j < n ? j : 0;
                float wt = __shfl_sync(0xffffffffu, ex, jj);
                int s2 = __shfl_sync(0xffffffffu, src, jj);
                if (j < n) {
                    float4 v = *(const float4*)&hs_in[(size_t)s2 * H + li * 4];
                    acc.x += v.x * wt; acc.y += v.y * wt; acc.z += v.z * wt; acc.w += v.w * wt;
                }
            }
        }
        acc.x += __shfl_down_sync(0xffffffffu, acc.x, 16);
        acc.y += __shfl_down_sync(0xffffffffu, acc.y, 16);
        acc.z += __shfl_down_sync(0xffffffffu, acc.z, 16);
        acc.w += __shfl_down_sync(0xffffffffu, acc.w, 16);
        if (lane < 16) {
            float sinv = deg > 0 ? 1.f / ssum : 0.f;
            int row = (wid << 3) + i;
            shHT[li * 4 + 0][row] = fmaxf(acc.x * sinv + bv.x, 0.f);
            shHT[li * 4 + 1][row] = fmaxf(acc.y * sinv + bv.y, 0.f);
            shHT[li * 4 + 2][row] = fmaxf(acc.z * sinv + bv.z, 0.f);
            shHT[li * 4 + 3][row] = fmaxf(acc.w * sinv + bv.w, 0.f);
        }
    }
    __syncthreads();

    // GEMM: hs_next = shHT^T @ W, fused attention epilogue (f32x2)
    int rg = tid >> 4, cg = tid & 15;
    int row0 = rg << 2, col0 = cg << 2;
    float as0 = atts[col0], as1 = atts[col0 + 1], as2 = atts[col0 + 2], as3 = atts[col0 + 3];
    float ad0 = attd[col0], ad1 = attd[col0 + 1], ad2 = attd[col0 + 2], ad3 = attd[col0 + 3];

    unsigned long long acc2[4][2] = {};
    #pragma unroll 8
    for (int k = 0; k < H; k++) {
        float4 av = *(const float4*)&shHT[k][row0];
        ulonglong2 wv = *(const ulonglong2*)&shW[k][col0];
        unsigned long long a0 = pack2(av.x), a1 = pack2(av.y);
        unsigned long long a2 = pack2(av.z), a3 = pack2(av.w);
        ffma2(acc2[0][0], a0, wv.x); ffma2(acc2[0][1], a0, wv.y);
        ffma2(acc2[1][0], a1, wv.x); ffma2(acc2[1][1], a1, wv.y);
        ffma2(acc2[2][0], a2, wv.x); ffma2(acc2[2][1], a2, wv.y);
        ffma2(acc2[3][0], a3, wv.x); ffma2(acc2[3][1], a3, wv.y);
    }

    #pragma unroll
    for (int xx = 0; xx < 4; xx++) {
        float2 p0 = unpack2(acc2[xx][0]);
        float2 p1 = unpack2(acc2[xx][1]);
        float ps = p0.x * as0 + p0.y * as1 + p1.x * as2 + p1.y * as3;
        float pd = p0.x * ad0 + p0.y * ad1 + p1.x * ad2 + p1.y * ad3;
        #pragma unroll
        for (int off = 8; off; off >>= 1) {
            ps += __shfl_xor_sync(0xffffffffu, ps, off);
            pd += __shfl_xor_sync(0xffffffffu, pd, off);
        }
        if ((tid & 15) == 0) {
            as_out[r0 + row0 + xx] = ps;
            ad_out[r0 + row0 + xx] = pd;
        }
        *(float4*)&hs_out[(size_t)(r0 + row0 + xx) * H + col0] =
            make_float4(p0.x, p0.y, p1.x, p1.y);
    }
}

// ---------------- well tail: edge aggregation + wc_bias + MLP, one block per well ----------------
__global__ __launch_bounds__(64) void well_tail(
    int buf_in,
    const float* __restrict__ wc_bias,
    const float* __restrict__ W1,
    const float* __restrict__ b1,
    const float* __restrict__ W2,
    const float* __restrict__ b2,
    float* __restrict__ out)
{
    __shared__ float hwell[64];
    __shared__ float t1[64];
    int r = blockIdx.x;
    int tid = threadIdx.x;
    const float* hs_in = g_hs + (size_t)buf_in * HS_STRIDE;
    const float* as_in = g_as + (size_t)buf_in * N_CELL;

    if (tid < 32) {
        int lane = tid;
        int half = lane >> 4, li = lane & 15;
        int beg = g_woff[r], end = g_woff[r + 1];
        int deg = end - beg;
        float adv = g_adw[r];
        float ssum = 0.f;
        float4 acc = make_float4(0.f, 0.f, 0.f, 0.f);

        for (int base = 0; base < deg; base += 32) {
            int n = min(32, deg - base);
            float ex = 0.f;
            int src = 0;
            if (lane < n) {
                src = g_wsrcp[beg + base + lane];
                float al = as_in[src] + adv;
                al = al > 0.f ? al : NEG_SLOPE * al;
                ex = __expf(al);
            }
            float cs = ex;
            #pragma unroll
            for (int off = 16; off; off >>= 1) cs += __shfl_xor_sync(0xffffffffu, cs, off);
            ssum += cs;
            int iters = (n + 1) >> 1;
            for (int t = 0; t < iters; t++) {
                int j = 2 * t + half;
                int jj = j < n ? j : 0;
                float wt = __shfl_sync(0xffffffffu, ex, jj);
                int s2 = __shfl_sync(0xffffffffu, src, jj);
                if (j < n) {
                    float4 v = *(const float4*)&hs_in[(size_t)s2 * H + li * 4];
                    acc.x += v.x * wt; acc.y += v.y * wt; acc.z += v.z * wt; acc.w += v.w * wt;
                }
            }
        }
        acc.x += __shfl_down_sync(0xffffffffu, acc.x, 16);
        acc.y += __shfl_down_sync(0xffffffffu, acc.y, 16);
        acc.z += __shfl_down_sync(0xffffffffu, acc.z, 16);
        acc.w += __shfl_down_sync(0xffffffffu, acc.w, 16);
        if (lane < 16) {
            float sinv = deg > 0 ? 1.f / ssum : 0.f;
            float4 wb = ((const float4*)wc_bias)[li];
            hwell[li * 4 + 0] = acc.x * sinv + wb.x;
            hwell[li * 4 + 1] = acc.y * sinv + wb.y;
            hwell[li * 4 + 2] = acc.z * sinv + wb.z;
            hwell[li * 4 + 3] = acc.w * sinv + wb.w;
        }
    }
    __syncthreads();

    float a = b1[tid];
    for (int k = 0; k < H; k++) a += hwell[k] * W1[k * H + tid];
    t1[tid] = fmaxf(a, 0.f);
    __syncthreads();
    for (int o = tid; o < 75; o += 64) {
        float acc = b2[o];
        for (int k = 0; k < H; k++) acc += t1[k] * W2[k * 75 + o];
        out[r * 75 + o] = acc;
    }
}

// ---------------- launcher ----------------
extern "C" void kernel_launch(void* const* d_in, const int* in_sizes, int n_in,
                              void* d_out, int out_size) {
    const void* cc_idx = nullptr;
    const void* cw_idx = nullptr;
    const float *cell_x = nullptr, *attr = nullptr, *W_cell_emb = nullptr,
                *W_well_emb = nullptr, *mlp_W2 = nullptr, *mlp_b2 = nullptr;
    const float* a12288[2] = {nullptr, nullptr};
    const float* a4096[3]  = {nullptr, nullptr, nullptr};
    const float* a192[4]   = {nullptr, nullptr, nullptr, nullptr};
    const float* a64[8]    = {nullptr, nullptr, nullptr, nullptr,
                              nullptr, nullptr, nullptr, nullptr};
    int n12288 = 0, n4096 = 0, n192 = 0, n64 = 0;
    int fsz[40]; int nf = 0;

    for (int i = 0; i < n_in; i++) {
        int sz = in_sizes[i];
        const float* p = (const float*)d_in[i];
        switch (sz) {
            case 2 * E_CC: cc_idx = d_in[i]; continue;
            case 2 * E_CW: cw_idx = d_in[i]; continue;
            case 2400000:  cell_x = p; break;
            case 1600000:  attr = p; break;
            case 768:      W_cell_emb = p; break;
            case 512:      W_well_emb = p; break;
            case 4800:     mlp_W2 = p; break;
            case 75:       mlp_b2 = p; break;
            case 12288:    if (n12288 < 2) a12288[n12288++] = p; break;
            case 4096:     if (n4096 < 3)  a4096[n4096++]   = p; break;
            case 192:      if (n192 < 4)   a192[n192++]     = p; break;
            case 64:       if (n64 < 8)    a64[n64++]       = p; break;
            default: break;
        }
        if (nf < 40) fsz[nf++] = sz;
    }

    int ord = 0;
    if (nf > 0 && fsz[0] == 768) ord = 1;
    else if (nf > 3 && fsz[0] == 64 && fsz[3] == 1600000) ord = 2;

    const float* conv_lin      = a12288[0];
    const float* conv_lin_edge = a12288[1];

    const float *conv_att_src, *conv_att_dst, *conv_att_edge, *conv_bias;
    if (ord == 0) { conv_att_src = a192[0]; conv_att_dst = a192[1];
                    conv_att_edge = a192[2]; conv_bias = a192[3]; }
    else          { conv_att_dst = a192[0]; conv_att_edge = a192[1];
                    conv_att_src = a192[2]; conv_bias = a192[3]; }

    const float *well_x, *wc_lin, *mlp_W1;
    if (ord == 0) { well_x = a4096[0]; wc_lin = a4096[1]; mlp_W1 = a4096[2]; }
    else          { mlp_W1 = a4096[0]; wc_lin = a4096[1]; well_x = a4096[2]; }

    const float *b_cell_emb, *b_well_emb, *W_edge_emb, *b_edge_emb,
                *wc_att_src, *wc_att_dst, *wc_bias, *mlp_b1;
    if (ord == 0) {
        b_cell_emb = a64[0]; b_well_emb = a64[1]; W_edge_emb = a64[2];
        b_edge_emb = a64[3]; wc_att_src = a64[4]; wc_att_dst = a64[5];
        wc_bias = a64[6]; mlp_b1 = a64[7];
    } else if (ord == 1) {
        W_edge_emb = a64[0]; b_cell_emb = a64[1]; b_edge_emb = a64[2];
        b_well_emb = a64[3]; mlp_b1 = a64[4]; wc_att_dst = a64[5];
        wc_att_src = a64[6]; wc_bias = a64[7];
    } else {
        b_cell_emb = a64[0]; b_edge_emb = a64[1]; b_well_emb = a64[2];
        mlp_b1 = a64[3]; W_edge_emb = a64[4]; wc_att_dst = a64[5];
        wc_att_src = a64[6]; wc_bias = a64[7];
    }

    // one-time host-side resources (no device memory)
    static cudaStream_t s_side = nullptr;
    static cudaEvent_t e_det = nullptr, e_csr = nullptr;
    if (!s_side) {
        cudaStreamCreateWithFlags(&s_side, cudaStreamNonBlocking);
        cudaEventCreateWithFlags(&e_det, cudaEventDisableTiming);
        cudaEventCreateWithFlags(&e_csr, cudaEventDisableTiming);
    }

    const int NBLK_SCAN = (N_CELL + 1023) / 1024;   // 196
    const int NB_EALL = (E_CC + E_CW) / 256;        // 6506

    // main: setup
    setup<<<8 + (N_CELL + 255) / 256, 256>>>(
        W_edge_emb, b_edge_emb, conv_lin_edge, conv_att_edge,
        W_cell_emb, b_cell_emb, conv_lin, cc_idx, cw_idx);
    cudaEventRecord(e_det, 0);

    // side: CSR build
    cudaStreamWaitEvent(s_side, e_det, 0);
    hist_all<<<NB_EALL, 256, 0, s_side>>>(cc_idx, cw_idx);
    scan1<<<NBLK_SCAN, 1024, 0, s_side>>>();
    scan2p<<<1, 256, 0, s_side>>>(NBLK_SCAN);
    scan3w<<<392, 512, 0, s_side>>>();
    scatter_all<<<NB_EALL, 256, 0, s_side>>>(cc_idx, cw_idx, attr);
    cudaEventRecord(e_csr, s_side);

    // main (overlaps CSR): layer-0 GEMM (writes buf 0) + well prep
    gemm12<<<N_TILE, 256>>>(cell_x, conv_att_src, conv_att_dst);
    well_prep<<<N_WELL, 64>>>(well_x, W_well_emb, b_well_emb, wc_lin, wc_att_dst);

    // join, then fused edge+gemm chain (ping-pong buffers: 0->1->0->1)
    cudaStreamWaitEvent(0, e_csr, 0);
    edge_gemm<<<N_TILE, 256>>>(0, 0, conv_lin + 1 * H * H,
                               conv_att_src + 64, conv_att_dst + 64, conv_bias);
    edge_gemm<<<N_TILE, 256>>>(1, 1, conv_lin + 2 * H * H,
                               conv_att_src + 128, conv_att_dst + 128, conv_bias + 64);
    edge_gemm<<<N_TILE, 256>>>(2, 0, wc_lin,
                               wc_att_src, wc_att_dst, conv_bias + 128);
    well_tail<<<N_WELL, 64>>>(1, wc_bias, mlp_W1, mlp_b1, mlp_W2, mlp_b2,
                              (float*)d_out);
}